// round 1
// baseline (speedup 1.0000x reference)
#include <cuda_runtime.h>
#include <cuda_bf16.h>
#include <math.h>

// ---------------------------------------------------------------------------
// LSTM: S=512, B=64, I=256, H=512
// out = [h_seq (S,B,H) | h_final (B,H) | c_final (B,H)]  (fp32)
// ---------------------------------------------------------------------------

#define S_LEN 512
#define BATCH 64
#define IN_DIM 256
#define HID 512
#define G4 2048              // 4*H
#define BH (BATCH*HID)       // 32768
#define BG (BATCH*G4)        // 131072
#define HPAD 516             // padded row stride (floats) for conflict-free smem

// -------------------- device scratch (static: no allocs allowed) ------------
__device__ float g_xp[(size_t)S_LEN * BATCH * G4];   // 256 MB: x@Wx + bx + bh
__device__ float g_Wx[IN_DIM * G4];                  // 2 MB packed (K x 4H)
__device__ float g_WhT[(size_t)G4 * HID];            // 4 MB: WhT[col][k]
__device__ float g_bias[G4];                         // bx + bh
__device__ unsigned int g_bar;

// -------------------- f32x2 helpers (Blackwell packed fp32) -----------------
__device__ __forceinline__ void fma2(unsigned long long& d,
                                     unsigned long long a,
                                     unsigned long long b) {
    asm("fma.rn.f32x2 %0, %1, %2, %0;" : "+l"(d) : "l"(a), "l"(b));
}
__device__ __forceinline__ unsigned long long dup2(float a) {
    unsigned long long d;
    asm("mov.b64 %0, {%1, %1};" : "=l"(d) : "f"(a));
    return d;
}
__device__ __forceinline__ float sum2(unsigned long long v) {
    float lo, hi;
    asm("mov.b64 {%0, %1}, %2;" : "=f"(lo), "=f"(hi) : "l"(v));
    return lo + hi;
}

// -------------------- init / pack kernels -----------------------------------
__global__ void bar_init_kernel() { g_bar = 0u; }

__global__ void pack_wx_kernel(
    const float* __restrict__ Wf, const float* __restrict__ Wi,
    const float* __restrict__ Wo, const float* __restrict__ Wg,
    const float* __restrict__ bxf, const float* __restrict__ bhf,
    const float* __restrict__ bxi, const float* __restrict__ bhi,
    const float* __restrict__ bxo, const float* __restrict__ bho,
    const float* __restrict__ bxg, const float* __restrict__ bhg)
{
    int idx = blockIdx.x * blockDim.x + threadIdx.x;
    if (idx < IN_DIM * G4) {
        int k = idx >> 11;          // /2048
        int col = idx & 2047;
        int g = col >> 9;
        int jj = col & 511;
        const float* W = (g == 0) ? Wf : (g == 1) ? Wi : (g == 2) ? Wo : Wg;
        g_Wx[idx] = W[k * HID + jj];
    }
    if (idx < G4) {
        int g = idx >> 9, jj = idx & 511;
        const float* bx = (g == 0) ? bxf : (g == 1) ? bxi : (g == 2) ? bxo : bxg;
        const float* bh = (g == 0) ? bhf : (g == 1) ? bhi : (g == 2) ? bho : bhg;
        g_bias[idx] = bx[jj] + bh[jj];
    }
}

__global__ void pack_wh_kernel(
    const float* __restrict__ Wf, const float* __restrict__ Wi,
    const float* __restrict__ Wo, const float* __restrict__ Wg)
{
    int idx = blockIdx.x * blockDim.x + threadIdx.x;
    if (idx < G4 * HID) {
        int col = idx >> 9;         // 0..2047
        int k   = idx & 511;
        int g   = col >> 9;
        int jj  = col & 511;
        const float* W = (g == 0) ? Wf : (g == 1) ? Wi : (g == 2) ? Wo : Wg;
        g_WhT[idx] = W[k * HID + jj];   // WhT[col][k] = Wh[k][col]
    }
}

// -------------------- xproj: xp = x @ Wx_cat + bias --------------------------
// M=32768, N=2048, K=256. Block tile 128x64, BK=16, 256 threads, TM=8, TN=4.
__global__ __launch_bounds__(256) void xproj_kernel(const float* __restrict__ x)
{
    __shared__ float As[16][132];   // transposed A tile, padded
    __shared__ float Bs[16][64];

    const int tid = threadIdx.x;
    const int tx = tid & 15;        // N direction (x4)
    const int ty = tid >> 4;        // M direction (x8)
    const int bm = blockIdx.y * 128;
    const int bn = blockIdx.x * 64;

    unsigned long long acc[8][2];
#pragma unroll
    for (int i = 0; i < 8; i++) { acc[i][0] = 0ull; acc[i][1] = 0ull; }

    const int a_m = tid >> 2;            // 0..63
    const int a_k = (tid & 3) << 2;      // 0,4,8,12
    const int b_r = tid >> 4;            // 0..15
    const int b_c = (tid & 15) << 2;

    const float* Aptr = x + (size_t)bm * IN_DIM;

    for (int kt = 0; kt < IN_DIM; kt += 16) {
        float4 av0 = *(const float4*)(Aptr + (size_t)a_m * IN_DIM + kt + a_k);
        float4 av1 = *(const float4*)(Aptr + (size_t)(a_m + 64) * IN_DIM + kt + a_k);
        float4 bv  = *(const float4*)(g_Wx + (size_t)(kt + b_r) * G4 + bn + b_c);

        As[a_k + 0][a_m] = av0.x; As[a_k + 1][a_m] = av0.y;
        As[a_k + 2][a_m] = av0.z; As[a_k + 3][a_m] = av0.w;
        As[a_k + 0][a_m + 64] = av1.x; As[a_k + 1][a_m + 64] = av1.y;
        As[a_k + 2][a_m + 64] = av1.z; As[a_k + 3][a_m + 64] = av1.w;
        *(float4*)&Bs[b_r][b_c] = bv;
        __syncthreads();

#pragma unroll
        for (int kk = 0; kk < 16; kk++) {
            float4 a0 = *(const float4*)&As[kk][ty * 8];
            float4 a1 = *(const float4*)&As[kk][ty * 8 + 4];
            ulonglong2 bb = *(const ulonglong2*)&Bs[kk][tx * 4];
            float av[8] = {a0.x, a0.y, a0.z, a0.w, a1.x, a1.y, a1.z, a1.w};
#pragma unroll
            for (int i = 0; i < 8; i++) {
                unsigned long long ad = dup2(av[i]);
                fma2(acc[i][0], ad, bb.x);
                fma2(acc[i][1], ad, bb.y);
            }
        }
        __syncthreads();
    }

    const int n0 = bn + tx * 4;
    float4 bias = *(const float4*)&g_bias[n0];
#pragma unroll
    for (int i = 0; i < 8; i++) {
        float l0, h0, l1, h1;
        asm("mov.b64 {%0, %1}, %2;" : "=f"(l0), "=f"(h0) : "l"(acc[i][0]));
        asm("mov.b64 {%0, %1}, %2;" : "=f"(l1), "=f"(h1) : "l"(acc[i][1]));
        float4 outv = make_float4(l0 + bias.x, h0 + bias.y, l1 + bias.z, h1 + bias.w);
        int m = bm + ty * 8 + i;
        *(float4*)&g_xp[(size_t)m * G4 + n0] = outv;
    }
}

// -------------------- recurrence: persistent, grid-barrier ------------------
// 128 CTAs x 256 threads. CTA owns hidden units j in [cta*4, cta*4+4).
// Thread = (b, jl): b=tid>>2, jl=tid&3. c lives in a register.
// smem: h_s[64][HPAD] (full h, reloaded per step) + wh_s[16][HPAD] (cached Wh slice)
#define NCTA 128
#define REC_SMEM ((64 * HPAD + 16 * HPAD) * 4)

__global__ __launch_bounds__(256, 1) void lstm_rec_kernel(float* __restrict__ out)
{
    extern __shared__ float sm[];
    float* h_s  = sm;                 // 64 * HPAD
    float* wh_s = sm + 64 * HPAD;     // 16 * HPAD

    const int tid = threadIdx.x;
    const int b   = tid >> 2;
    const int jl  = tid & 3;
    const int cta = blockIdx.x;
    const int j   = (cta << 2) + jl;

    // Load Wh slice once: wh_s[g*4+jr][k] = Wh[k][g*512 + cta*4 + jr]
    for (int idx = tid; idx < 16 * 128; idx += 256) {
        int r  = idx >> 7;
        int k4 = (idx & 127) << 2;
        int g  = r >> 2, jr = r & 3;
        int col = g * HID + (cta << 2) + jr;
        float4 v = *(const float4*)&g_WhT[(size_t)col * HID + k4];
        *(float4*)&wh_s[r * HPAD + k4] = v;
    }

    const ulonglong2* hp = (const ulonglong2*)(h_s + b * HPAD);
    const ulonglong2* w0 = (const ulonglong2*)(wh_s + (0 + jl) * HPAD);
    const ulonglong2* w1 = (const ulonglong2*)(wh_s + (4 + jl) * HPAD);
    const ulonglong2* w2 = (const ulonglong2*)(wh_s + (8 + jl) * HPAD);
    const ulonglong2* w3 = (const ulonglong2*)(wh_s + (12 + jl) * HPAD);

    float cval = 0.f;

    for (int t = 0; t < S_LEN; t++) {
        if (t > 0) {
            const float4* src = (const float4*)(out + (size_t)(t - 1) * BH);
#pragma unroll
            for (int i = 0; i < 32; i++) {          // 8192 float4 / 256 thr
                int idx = tid + (i << 8);
                int row = idx >> 7;
                int col = (idx & 127) << 2;
                *(float4*)&h_s[row * HPAD + col] = src[idx];
            }
        }
        __syncthreads();

        size_t xb = (size_t)t * BG + (size_t)b * G4 + j;
        float xf = g_xp[xb];
        float xi = g_xp[xb + 512];
        float xo = g_xp[xb + 1024];
        float xg = g_xp[xb + 1536];

        float gf, gi, go, gg;
        if (t > 0) {
            unsigned long long af = 0ull, ai = 0ull, ao = 0ull, ag = 0ull;
#pragma unroll 4
            for (int k = 0; k < 128; k++) {
                ulonglong2 hv = hp[k];
                ulonglong2 wf = w0[k];
                ulonglong2 wi = w1[k];
                ulonglong2 wo = w2[k];
                ulonglong2 wg = w3[k];
                fma2(af, hv.x, wf.x); fma2(af, hv.y, wf.y);
                fma2(ai, hv.x, wi.x); fma2(ai, hv.y, wi.y);
                fma2(ao, hv.x, wo.x); fma2(ao, hv.y, wo.y);
                fma2(ag, hv.x, wg.x); fma2(ag, hv.y, wg.y);
            }
            gf = sum2(af); gi = sum2(ai); go = sum2(ao); gg = sum2(ag);
        } else {
            gf = gi = go = gg = 0.f;
        }

        gf += xf; gi += xi; go += xo; gg += xg;
        float fg  = 1.f / (1.f + expf(-gf));
        float ig  = 1.f / (1.f + expf(-gi));
        float og  = 1.f / (1.f + expf(-go));
        float gt  = tanhf(gg);
        cval = fg * cval + ig * gt;
        float hval = og * tanhf(cval);

        out[(size_t)t * BH + b * HID + j] = hval;
        if (t == S_LEN - 1) {
            out[(size_t)S_LEN * BH + b * HID + j] = hval;          // h_final
            out[(size_t)S_LEN * BH + BH + b * HID + j] = cval;     // c_final
        }

        // ---- grid barrier (release/acquire on global counter) ----
        __syncthreads();
        if (tid == 0) {
            __threadfence();
            asm volatile("red.release.gpu.global.add.u32 [%0], 1;"
                         :: "l"(&g_bar) : "memory");
            unsigned target = (unsigned)(t + 1) * NCTA;
            unsigned v;
            do {
                asm volatile("ld.acquire.gpu.global.u32 %0, [%1];"
                             : "=r"(v) : "l"(&g_bar) : "memory");
            } while (v < target);
        }
        __syncthreads();
    }
}

// -------------------- launch ------------------------------------------------
extern "C" void kernel_launch(void* const* d_in, const int* in_sizes, int n_in,
                              void* d_out, int out_size)
{
    (void)in_sizes; (void)n_in; (void)out_size;
    const float* x   = (const float*)d_in[0];
    const float* Wxf = (const float*)d_in[1];
    const float* bxf = (const float*)d_in[2];
    const float* Whf = (const float*)d_in[3];
    const float* bhf = (const float*)d_in[4];
    const float* Wxi = (const float*)d_in[5];
    const float* bxi = (const float*)d_in[6];
    const float* Whi = (const float*)d_in[7];
    const float* bhi = (const float*)d_in[8];
    const float* Wxo = (const float*)d_in[9];
    const float* bxo = (const float*)d_in[10];
    const float* Who = (const float*)d_in[11];
    const float* bho = (const float*)d_in[12];
    const float* Wxg = (const float*)d_in[13];
    const float* bxg = (const float*)d_in[14];
    const float* Whg = (const float*)d_in[15];
    const float* bhg = (const float*)d_in[16];
    float* out = (float*)d_out;

    bar_init_kernel<<<1, 1>>>();
    pack_wx_kernel<<<(IN_DIM * G4 + 255) / 256, 256>>>(
        Wxf, Wxi, Wxo, Wxg, bxf, bhf, bxi, bhi, bxo, bho, bxg, bhg);
    pack_wh_kernel<<<(G4 * HID + 255) / 256, 256>>>(Whf, Whi, Who, Whg);

    dim3 gproj(G4 / 64, (S_LEN * BATCH) / 128);
    xproj_kernel<<<gproj, 256>>>(x);

    static bool attr_set = false;
    if (!attr_set) {
        cudaFuncSetAttribute(lstm_rec_kernel,
                             cudaFuncAttributeMaxDynamicSharedMemorySize, REC_SMEM);
        attr_set = true;
    }
    lstm_rec_kernel<<<NCTA, 256, REC_SMEM>>>(out);
}

// round 2
// speedup vs baseline: 1.1618x; 1.1618x over previous
#include <cuda_runtime.h>
#include <cuda_bf16.h>
#include <math.h>

// ---------------------------------------------------------------------------
// LSTM: S=512, B=64, I=256, H=512
// out = [h_seq (S,B,H) | h_final (B,H) | c_final (B,H)]  (fp32)
// ---------------------------------------------------------------------------

#define S_LEN 512
#define BATCH 64
#define IN_DIM 256
#define HID 512
#define G4 2048              // 4*H
#define BH (BATCH*HID)       // 32768
#define BG (BATCH*G4)        // 131072
#define HPAD 516             // padded row stride (floats) for conflict-free smem

// -------------------- device scratch (static: no allocs allowed) ------------
__device__ float g_xp[(size_t)S_LEN * BATCH * G4];   // 256 MB: x@Wx + bx + bh
__device__ float g_Wx[IN_DIM * G4];                  // 2 MB packed (K x 4H)
__device__ float g_WhT[(size_t)G4 * HID];            // 4 MB: WhT[col][k]
__device__ float g_bias[G4];                         // bx + bh
__device__ unsigned int g_bar;

// -------------------- f32x2 helpers (Blackwell packed fp32) -----------------
__device__ __forceinline__ void fma2(unsigned long long& d,
                                     unsigned long long a,
                                     unsigned long long b) {
    asm("fma.rn.f32x2 %0, %1, %2, %0;" : "+l"(d) : "l"(a), "l"(b));
}
__device__ __forceinline__ unsigned long long dup2(float a) {
    unsigned long long d;
    asm("mov.b64 %0, {%1, %1};" : "=l"(d) : "f"(a));
    return d;
}
__device__ __forceinline__ float sum2(unsigned long long v) {
    float lo, hi;
    asm("mov.b64 {%0, %1}, %2;" : "=f"(lo), "=f"(hi) : "l"(v));
    return lo + hi;
}

// fast activations: ex2.approx + rcp.approx (rel err ~1e-6, safe vs 1e-3 tol)
__device__ __forceinline__ float fast_exp(float x) {
    float e;
    asm("ex2.approx.f32 %0, %1;" : "=f"(e) : "f"(x * 1.4426950408889634f));
    return e;
}
__device__ __forceinline__ float fast_rcp(float x) {
    float r;
    asm("rcp.approx.f32 %0, %1;" : "=f"(r) : "f"(x));
    return r;
}
__device__ __forceinline__ float fast_sigmoid(float x) {
    return fast_rcp(1.f + fast_exp(-x));
}
__device__ __forceinline__ float fast_tanh(float x) {
    // tanh(x) = 2*sigmoid(2x) - 1
    return 2.f * fast_rcp(1.f + fast_exp(-2.f * x)) - 1.f;
}

__device__ __forceinline__ void cpasync16(unsigned dst, const void* src) {
    asm volatile("cp.async.cg.shared.global [%0], [%1], 16;"
                 :: "r"(dst), "l"(src));
}

// -------------------- init / pack kernels -----------------------------------
__global__ void bar_init_kernel() { g_bar = 0u; }

__global__ void pack_wx_kernel(
    const float* __restrict__ Wf, const float* __restrict__ Wi,
    const float* __restrict__ Wo, const float* __restrict__ Wg,
    const float* __restrict__ bxf, const float* __restrict__ bhf,
    const float* __restrict__ bxi, const float* __restrict__ bhi,
    const float* __restrict__ bxo, const float* __restrict__ bho,
    const float* __restrict__ bxg, const float* __restrict__ bhg)
{
    int idx = blockIdx.x * blockDim.x + threadIdx.x;
    if (idx < IN_DIM * G4) {
        int k = idx >> 11;          // /2048
        int col = idx & 2047;
        int g = col >> 9;
        int jj = col & 511;
        const float* W = (g == 0) ? Wf : (g == 1) ? Wi : (g == 2) ? Wo : Wg;
        g_Wx[idx] = W[k * HID + jj];
    }
    if (idx < G4) {
        int g = idx >> 9, jj = idx & 511;
        const float* bx = (g == 0) ? bxf : (g == 1) ? bxi : (g == 2) ? bxo : bxg;
        const float* bh = (g == 0) ? bhf : (g == 1) ? bhi : (g == 2) ? bho : bhg;
        g_bias[idx] = bx[jj] + bh[jj];
    }
}

__global__ void pack_wh_kernel(
    const float* __restrict__ Wf, const float* __restrict__ Wi,
    const float* __restrict__ Wo, const float* __restrict__ Wg)
{
    int idx = blockIdx.x * blockDim.x + threadIdx.x;
    if (idx < G4 * HID) {
        int col = idx >> 9;         // 0..2047
        int k   = idx & 511;
        int g   = col >> 9;
        int jj  = col & 511;
        const float* W = (g == 0) ? Wf : (g == 1) ? Wi : (g == 2) ? Wo : Wg;
        g_WhT[idx] = W[k * HID + jj];   // WhT[col][k] = Wh[k][col]
    }
}

// -------------------- xproj: xp = x @ Wx_cat + bias --------------------------
// M=32768, N=2048, K=256. Block tile 128x64, BK=16, 256 threads, TM=8, TN=4.
__global__ __launch_bounds__(256) void xproj_kernel(const float* __restrict__ x)
{
    __shared__ float As[16][132];   // transposed A tile, padded
    __shared__ float Bs[16][64];

    const int tid = threadIdx.x;
    const int tx = tid & 15;        // N direction (x4)
    const int ty = tid >> 4;        // M direction (x8)
    const int bm = blockIdx.y * 128;
    const int bn = blockIdx.x * 64;

    unsigned long long acc[8][2];
#pragma unroll
    for (int i = 0; i < 8; i++) { acc[i][0] = 0ull; acc[i][1] = 0ull; }

    const int a_m = tid >> 2;            // 0..63
    const int a_k = (tid & 3) << 2;      // 0,4,8,12
    const int b_r = tid >> 4;            // 0..15
    const int b_c = (tid & 15) << 2;

    const float* Aptr = x + (size_t)bm * IN_DIM;

    for (int kt = 0; kt < IN_DIM; kt += 16) {
        float4 av0 = *(const float4*)(Aptr + (size_t)a_m * IN_DIM + kt + a_k);
        float4 av1 = *(const float4*)(Aptr + (size_t)(a_m + 64) * IN_DIM + kt + a_k);
        float4 bv  = *(const float4*)(g_Wx + (size_t)(kt + b_r) * G4 + bn + b_c);

        As[a_k + 0][a_m] = av0.x; As[a_k + 1][a_m] = av0.y;
        As[a_k + 2][a_m] = av0.z; As[a_k + 3][a_m] = av0.w;
        As[a_k + 0][a_m + 64] = av1.x; As[a_k + 1][a_m + 64] = av1.y;
        As[a_k + 2][a_m + 64] = av1.z; As[a_k + 3][a_m + 64] = av1.w;
        *(float4*)&Bs[b_r][b_c] = bv;
        __syncthreads();

#pragma unroll
        for (int kk = 0; kk < 16; kk++) {
            float4 a0 = *(const float4*)&As[kk][ty * 8];
            float4 a1 = *(const float4*)&As[kk][ty * 8 + 4];
            ulonglong2 bb = *(const ulonglong2*)&Bs[kk][tx * 4];
            float av[8] = {a0.x, a0.y, a0.z, a0.w, a1.x, a1.y, a1.z, a1.w};
#pragma unroll
            for (int i = 0; i < 8; i++) {
                unsigned long long ad = dup2(av[i]);
                fma2(acc[i][0], ad, bb.x);
                fma2(acc[i][1], ad, bb.y);
            }
        }
        __syncthreads();
    }

    const int n0 = bn + tx * 4;
    float4 bias = *(const float4*)&g_bias[n0];
#pragma unroll
    for (int i = 0; i < 8; i++) {
        float l0, h0, l1, h1;
        asm("mov.b64 {%0, %1}, %2;" : "=f"(l0), "=f"(h0) : "l"(acc[i][0]));
        asm("mov.b64 {%0, %1}, %2;" : "=f"(l1), "=f"(h1) : "l"(acc[i][1]));
        float4 outv = make_float4(l0 + bias.x, h0 + bias.y, l1 + bias.z, h1 + bias.w);
        int m = bm + ty * 8 + i;
        *(float4*)&g_xp[(size_t)m * G4 + n0] = outv;
    }
}

// -------------------- recurrence: persistent, grid-barrier ------------------
// 128 CTAs x 256 threads. CTA owns hidden units j in [cta*4, cta*4+4)
// (16 gate columns: rows r = g*4+u, g=gate 0..3 (f,i,o,g), u=unit 0..3).
// Thread: bp = tid>>3 (batch pair 2bp,2bp+1), jl = tid&7 -> w rows jl, jl+8.
//   g1 = jl>>2 (0: gates f,o ; 1: gates i,g), u = jl&3.
// After dots, gate halves exchanged with partner tid^4 via shfl_xor.
// Thread owns c/h for batch (g1==0 ? b0 : b1), unit u.
#define NCTA 128
#define REC_SMEM ((64 * HPAD + 16 * HPAD) * 4)

__global__ __launch_bounds__(256, 1) void lstm_rec_kernel(float* __restrict__ out)
{
    extern __shared__ float sm[];
    float* h_s  = sm;                 // 64 * HPAD (h for all 64 batches)
    float* wh_s = sm + 64 * HPAD;     // 16 * HPAD (Wh slice, cached all steps)

    const int tid = threadIdx.x;
    const int bp  = tid >> 3;         // 0..31
    const int jl  = tid & 7;          // 0..7
    const int g1  = jl >> 2;          // 0 or 1
    const int u   = jl & 3;
    const int cta = blockIdx.x;
    const int b0  = bp << 1;
    const int b1  = b0 + 1;
    const int j   = (cta << 2) + u;   // hidden unit
    const int myb = g1 ? b1 : b0;

    // Load Wh slice once: wh_s[r][k] = Wh[k][ (r>>2)*512 + cta*4 + (r&3) ]
    for (int idx = tid; idx < 16 * 128; idx += 256) {
        int r  = idx >> 7;
        int k4 = (idx & 127) << 2;
        int g  = r >> 2, jr = r & 3;
        int col = g * HID + (cta << 2) + jr;
        float4 v = *(const float4*)&g_WhT[(size_t)col * HID + k4];
        *(float4*)&wh_s[r * HPAD + k4] = v;
    }
    __syncthreads();

    const ulonglong2* hp0 = (const ulonglong2*)(h_s + b0 * HPAD);
    const ulonglong2* hp1 = (const ulonglong2*)(h_s + b1 * HPAD);
    const ulonglong2* wq1 = (const ulonglong2*)(wh_s + jl * HPAD);
    const ulonglong2* wq2 = (const ulonglong2*)(wh_s + (jl + 8) * HPAD);

    const unsigned hbase = (unsigned)__cvta_generic_to_shared(h_s);

    // gate-column offsets within one (b) row of xp
    const int C1 = g1 * HID + j;          // gate g1 (f or i)
    const int C2 = C1 + 1024;             // gate g1+2 (o or g)
    const size_t xo00 = (size_t)b0 * G4 + C1;
    const size_t xo01 = (size_t)b0 * G4 + C2;
    const size_t xo10 = (size_t)b1 * G4 + C1;
    const size_t xo11 = (size_t)b1 * G4 + C2;

    // prefetch xp for t=0
    float c00 = g_xp[xo00], c01 = g_xp[xo01];
    float c10 = g_xp[xo10], c11 = g_xp[xo11];

    float cval = 0.f;

    for (int t = 0; t < S_LEN; t++) {
        if (t > 0) {
            // stage h(t-1) from out into smem via cp.async (no reg roundtrip)
            const float4* src = (const float4*)(out + (size_t)(t - 1) * BH);
#pragma unroll
            for (int i = 0; i < 32; i++) {          // 8192 float4 / 256 thr
                int idx = tid + (i << 8);
                int row = idx >> 7;
                int col = (idx & 127) << 2;
                cpasync16(hbase + (unsigned)(row * HPAD + col) * 4u,
                          (const void*)(src + idx));
            }
            asm volatile("cp.async.commit_group;");
            asm volatile("cp.async.wait_group 0;" ::: "memory");
            __syncthreads();
        }

        // prefetch xp for t+1 (hides DRAM latency under the dot loop)
        float n00 = 0.f, n01 = 0.f, n10 = 0.f, n11 = 0.f;
        if (t + 1 < S_LEN) {
            size_t nb = (size_t)(t + 1) * BG;
            n00 = g_xp[nb + xo00]; n01 = g_xp[nb + xo01];
            n10 = g_xp[nb + xo10]; n11 = g_xp[nb + xo11];
        }

        // dots: v[b][c] for b in {b0,b1}, c in {C1,C2}
        float v10, v11, v20, v21;
        if (t > 0) {
            unsigned long long a00 = 0ull, a01 = 0ull, a10 = 0ull, a11 = 0ull;
#pragma unroll 4
            for (int k = 0; k < 128; k++) {
                ulonglong2 h0 = hp0[k];
                ulonglong2 h1 = hp1[k];
                ulonglong2 w1 = wq1[k];
                ulonglong2 w2 = wq2[k];
                fma2(a00, h0.x, w1.x); fma2(a00, h0.y, w1.y);
                fma2(a01, h0.x, w2.x); fma2(a01, h0.y, w2.y);
                fma2(a10, h1.x, w1.x); fma2(a10, h1.y, w1.y);
                fma2(a11, h1.x, w2.x); fma2(a11, h1.y, w2.y);
            }
            v10 = sum2(a00) + c00;   // (b0, C1)
            v20 = sum2(a01) + c01;   // (b0, C2)
            v11 = sum2(a10) + c10;   // (b1, C1)
            v21 = sum2(a11) + c11;   // (b1, C2)
        } else {
            v10 = c00; v20 = c01; v11 = c10; v21 = c11;
        }
        c00 = n00; c01 = n01; c10 = n10; c11 = n11;

        // exchange gate halves with partner tid^4
        float s1 = g1 ? v10 : v11;
        float s2 = g1 ? v20 : v21;
        float r1 = __shfl_xor_sync(0xffffffffu, s1, 4);
        float r2 = __shfl_xor_sync(0xffffffffu, s2, 4);

        float gf = g1 ? r1  : v10;
        float gi = g1 ? v11 : r1;
        float go = g1 ? r2  : v20;
        float gg = g1 ? v21 : r2;

        float fg = fast_sigmoid(gf);
        float ig = fast_sigmoid(gi);
        float og = fast_sigmoid(go);
        float gt = fast_tanh(gg);
        cval = fg * cval + ig * gt;
        float hval = og * fast_tanh(cval);

        out[(size_t)t * BH + myb * HID + j] = hval;

        if (t < S_LEN - 1) {
            // ---- grid barrier: release-red + acquire-poll with backoff ----
            __syncthreads();
            if (tid == 0) {
                asm volatile("red.release.gpu.global.add.u32 [%0], 1;"
                             :: "l"(&g_bar) : "memory");
                unsigned target = (unsigned)(t + 1) * NCTA;
                unsigned v;
                while (true) {
                    asm volatile("ld.acquire.gpu.global.u32 %0, [%1];"
                                 : "=r"(v) : "l"(&g_bar) : "memory");
                    if (v >= target) break;
                    __nanosleep(32);
                }
            }
            __syncthreads();
        } else {
            out[(size_t)S_LEN * BH + myb * HID + j] = hval;          // h_final
            out[(size_t)S_LEN * BH + BH + myb * HID + j] = cval;     // c_final
        }
    }
}

// -------------------- launch ------------------------------------------------
extern "C" void kernel_launch(void* const* d_in, const int* in_sizes, int n_in,
                              void* d_out, int out_size)
{
    (void)in_sizes; (void)n_in; (void)out_size;
    const float* x   = (const float*)d_in[0];
    const float* Wxf = (const float*)d_in[1];
    const float* bxf = (const float*)d_in[2];
    const float* Whf = (const float*)d_in[3];
    const float* bhf = (const float*)d_in[4];
    const float* Wxi = (const float*)d_in[5];
    const float* bxi = (const float*)d_in[6];
    const float* Whi = (const float*)d_in[7];
    const float* bhi = (const float*)d_in[8];
    const float* Wxo = (const float*)d_in[9];
    const float* bxo = (const float*)d_in[10];
    const float* Who = (const float*)d_in[11];
    const float* bho = (const float*)d_in[12];
    const float* Wxg = (const float*)d_in[13];
    const float* bxg = (const float*)d_in[14];
    const float* Whg = (const float*)d_in[15];
    const float* bhg = (const float*)d_in[16];
    float* out = (float*)d_out;

    bar_init_kernel<<<1, 1>>>();
    pack_wx_kernel<<<(IN_DIM * G4 + 255) / 256, 256>>>(
        Wxf, Wxi, Wxo, Wxg, bxf, bhf, bxi, bhi, bxo, bho, bxg, bhg);
    pack_wh_kernel<<<(G4 * HID + 255) / 256, 256>>>(Whf, Whi, Who, Whg);

    dim3 gproj(G4 / 64, (S_LEN * BATCH) / 128);
    xproj_kernel<<<gproj, 256>>>(x);

    static bool attr_set = false;
    if (!attr_set) {
        cudaFuncSetAttribute(lstm_rec_kernel,
                             cudaFuncAttributeMaxDynamicSharedMemorySize, REC_SMEM);
        attr_set = true;
    }
    lstm_rec_kernel<<<NCTA, 256, REC_SMEM>>>(out);
}